// round 15
// baseline (speedup 1.0000x reference)
#include <cuda_runtime.h>
#include <cstdint>

#define NB 16
#define NL 1024
#define ND 512
#define NH 256
#define NK 4
#define NROWS (NB * NL)   // 16384

// ---------------- scratch (static device globals; no allocs) ----------------
__device__ float g_sel [NROWS * NK];     // softmax selections     (256 KB)
__device__ float g_uin [NROWS * NH];     // x @ W_B^T              (16 MB)
__device__ float g_invn[NROWS * NH];     // 1/norm per (row, j)    (16 MB)

// ---------------- helpers ----------------------------------------------------
__device__ __forceinline__ float fast_lg2(float x) {
    float r; asm("lg2.approx.f32 %0, %1;" : "=f"(r) : "f"(x)); return r;
}
__device__ __forceinline__ float fast_ex2(float x) {
    float r; asm("ex2.approx.f32 %0, %1;" : "=f"(r) : "f"(x)); return r;
}
__device__ __forceinline__ uint32_t smem_u32(const void* p) {
    uint32_t a;
    asm("{ .reg .u64 t; cvta.to.shared.u64 t, %1; cvt.u32.u64 %0, t; }"
        : "=r"(a) : "l"(p));
    return a;
}
__device__ __forceinline__ uint32_t mapa_u32(uint32_t a, uint32_t r) {
    uint32_t d;
    asm("mapa.shared::cluster.u32 %0, %1, %2;" : "=r"(d) : "r"(a), "r"(r));
    return d;
}
__device__ __forceinline__ void mbar_wait(uint32_t mb, uint32_t ph) {
    asm volatile(
        "{\n\t.reg .pred p;\n"
        "WL%=:\n\t"
        "mbarrier.try_wait.parity.acquire.cluster.shared::cta.b64 p, [%0], %1;\n\t"
        "@!p bra WL%=;\n\t}"
        :: "r"(mb), "r"(ph) : "memory");
}

// ---------------- kernel 1: selection logits + softmax ----------------------
__global__ __launch_bounds__(256) void sel_kernel(
    const float* __restrict__ x, const float* __restrict__ Wsel,
    const float* __restrict__ bsel)
{
    __shared__ float Ws[NK * ND];
    for (int i = threadIdx.x; i < NK * ND; i += blockDim.x) Ws[i] = Wsel[i];
    __syncthreads();

    int w = threadIdx.x >> 5, l = threadIdx.x & 31;
    int row = blockIdx.x * 8 + w;
    const float* xr = x + row * ND;

    float p0 = 0.f, p1 = 0.f, p2 = 0.f, p3 = 0.f;
    for (int d = l; d < ND; d += 32) {
        float xv = xr[d];
        p0 += xv * Ws[d];
        p1 += xv * Ws[ND + d];
        p2 += xv * Ws[2 * ND + d];
        p3 += xv * Ws[3 * ND + d];
    }
#pragma unroll
    for (int o = 16; o > 0; o >>= 1) {
        p0 += __shfl_xor_sync(0xffffffffu, p0, o);
        p1 += __shfl_xor_sync(0xffffffffu, p1, o);
        p2 += __shfl_xor_sync(0xffffffffu, p2, o);
        p3 += __shfl_xor_sync(0xffffffffu, p3, o);
    }
    if (l == 0) {
        float l0 = p0 + bsel[0], l1 = p1 + bsel[1], l2 = p2 + bsel[2], l3 = p3 + bsel[3];
        float m = fmaxf(fmaxf(l0, l1), fmaxf(l2, l3));
        float e0 = __expf(l0 - m), e1 = __expf(l1 - m), e2 = __expf(l2 - m), e3 = __expf(l3 - m);
        float inv = 1.0f / (e0 + e1 + e2 + e3);
        float4 out = make_float4(e0 * inv, e1 * inv, e2 * inv, e3 * inv);
        *reinterpret_cast<float4*>(&g_sel[row * NK]) = out;
    }
}

// ---------------- kernel 2: u = x @ W_B^T  (128x128 tile, 8x8/thread) -------
__global__ __launch_bounds__(256, 2) void uin_kernel(
    const float* __restrict__ X, const float* __restrict__ Wb)
{
    __shared__ float Xs[16][128];
    __shared__ float Wt[16][128];
    int m0 = blockIdx.x * 128;
    int n0 = blockIdx.y * 128;
    int tid = threadIdx.x;
    int tx = tid & 15, ty = tid >> 4;
    int lr = tid >> 2, lq = tid & 3;

    float acc[8][8];
#pragma unroll
    for (int r = 0; r < 8; r++)
#pragma unroll
        for (int c = 0; c < 8; c++) acc[r][c] = 0.f;

    for (int k0 = 0; k0 < ND; k0 += 16) {
        float4 x0 = *reinterpret_cast<const float4*>(&X [(m0 + lr)      * ND + k0 + lq * 4]);
        float4 x1 = *reinterpret_cast<const float4*>(&X [(m0 + 64 + lr) * ND + k0 + lq * 4]);
        float4 w0 = *reinterpret_cast<const float4*>(&Wb[(n0 + lr)      * ND + k0 + lq * 4]);
        float4 w1 = *reinterpret_cast<const float4*>(&Wb[(n0 + 64 + lr) * ND + k0 + lq * 4]);
        __syncthreads();
        Xs[lq * 4 + 0][lr] = x0.x; Xs[lq * 4 + 1][lr] = x0.y;
        Xs[lq * 4 + 2][lr] = x0.z; Xs[lq * 4 + 3][lr] = x0.w;
        Xs[lq * 4 + 0][64 + lr] = x1.x; Xs[lq * 4 + 1][64 + lr] = x1.y;
        Xs[lq * 4 + 2][64 + lr] = x1.z; Xs[lq * 4 + 3][64 + lr] = x1.w;
        Wt[lq * 4 + 0][lr] = w0.x; Wt[lq * 4 + 1][lr] = w0.y;
        Wt[lq * 4 + 2][lr] = w0.z; Wt[lq * 4 + 3][lr] = w0.w;
        Wt[lq * 4 + 0][64 + lr] = w1.x; Wt[lq * 4 + 1][64 + lr] = w1.y;
        Wt[lq * 4 + 2][64 + lr] = w1.z; Wt[lq * 4 + 3][64 + lr] = w1.w;
        __syncthreads();
#pragma unroll
        for (int kk = 0; kk < 16; kk++) {
            float4 a0 = *reinterpret_cast<const float4*>(&Xs[kk][ty * 8]);
            float4 a1 = *reinterpret_cast<const float4*>(&Xs[kk][ty * 8 + 4]);
            float4 b0 = *reinterpret_cast<const float4*>(&Wt[kk][tx * 8]);
            float4 b1 = *reinterpret_cast<const float4*>(&Wt[kk][tx * 8 + 4]);
            float av[8] = {a0.x, a0.y, a0.z, a0.w, a1.x, a1.y, a1.z, a1.w};
            float bv[8] = {b0.x, b0.y, b0.z, b0.w, b1.x, b1.y, b1.z, b1.w};
#pragma unroll
            for (int r = 0; r < 8; r++)
#pragma unroll
                for (int c = 0; c < 8; c++)
                    acc[r][c] = fmaf(av[r], bv[c], acc[r][c]);
        }
    }
#pragma unroll
    for (int r = 0; r < 8; r++) {
        float4 o0 = make_float4(acc[r][0], acc[r][1], acc[r][2], acc[r][3]);
        float4 o1 = make_float4(acc[r][4], acc[r][5], acc[r][6], acc[r][7]);
        *reinterpret_cast<float4*>(&g_uin[(m0 + ty * 8 + r) * NH + n0 + tx * 8])     = o0;
        *reinterpret_cast<float4*>(&g_uin[(m0 + ty * 8 + r) * NH + n0 + tx * 8 + 4]) = o1;
    }
}

// ---------------- kernel 3: inv_norm pre-pass (register-resident A) ---------
__global__ __launch_bounds__(256, 3) void norm_kernel(const float* __restrict__ A)
{
    int jbase = blockIdx.x * 8;
    int w = threadIdx.x >> 5, l = threadIdx.x & 31;
    int j = jbase + w;

    float4 Ar[8];
#pragma unroll
    for (int r = 0; r < 8; r++)
        Ar[r] = reinterpret_cast<const float4*>(A)[(l + 32 * r) * NH + j];

    const int rows_per_blk = NROWS / 64;       // 256
    const int row0 = blockIdx.y * rows_per_blk;
    const float ninv = -1.0f / 1.2f;

    for (int row = row0; row < row0 + rows_per_blk; row += 2) {
        float4 sA = __ldg(reinterpret_cast<const float4*>(&g_sel[row * NK]));
        float4 sB = __ldg(reinterpret_cast<const float4*>(&g_sel[(row + 1) * NK]));
        float accA = 0.f, accB = 0.f;
#pragma unroll
        for (int r = 0; r < 8; r++) {
            float a = fmaf(sA.x, Ar[r].x, fmaf(sA.y, Ar[r].y,
                      fmaf(sA.z, Ar[r].z, sA.w * Ar[r].w)));
            float b = fmaf(sB.x, Ar[r].x, fmaf(sB.y, Ar[r].y,
                      fmaf(sB.z, Ar[r].z, sB.w * Ar[r].w)));
            accA += fast_ex2(0.6f * fast_lg2(a * a));
            accB += fast_ex2(0.6f * fast_lg2(b * b));
        }
#pragma unroll
        for (int o = 16; o > 0; o >>= 1) {
            accA += __shfl_xor_sync(0xffffffffu, accA, o);
            accB += __shfl_xor_sync(0xffffffffu, accB, o);
        }
        if (l == 0) {
            g_invn[row * NH + j]       = fast_ex2(fast_lg2(accA) * ninv);
            g_invn[(row + 1) * NH + j] = fast_ex2(fast_lg2(accB) * ninv);
        }
    }
}

// ---------------- kernel 4: scan, 1 batch/cluster, k-DECOMPOSED -------------
// 16 clusters x 8 CTAs = 128 CTAs (fully wave-1 resident, proven in R5).
// Per-iter FFMA issue halves vs R14 (512 cyc/SMSP): thread handles one batch,
// 64 FFMA k-chains + 4 combine. warp0-only tail (prefetch inv/u, mbar wait,
// expect(t+2), pbuf consume, out store, h/y update). Protocol unchanged.
__global__ __launch_bounds__(512, 1) __cluster_dims__(8, 1, 1)
void scan_kernel(const float* __restrict__ A, float* __restrict__ out)
{
    __shared__ float y_sm[32];
    __shared__ float pbuf[2][8][32];                  // [parity][src][row]
    __shared__ __align__(8) unsigned long long mbar[2];

    int tid = threadIdx.x;
    uint32_t rank;
    asm("mov.u32 %0, %%cluster_ctarank;" : "=r"(rank));
    int b = blockIdx.x >> 3;                 // cluster id == batch
    int jbase = (int)rank * 32;
    int i = tid >> 1, half = tid & 1;

    float4 Areg[16];
#pragma unroll
    for (int q = 0; q < 16; q++)
        Areg[q] = reinterpret_cast<const float4*>(A)[i * NH + jbase + half * 16 + q];

    uint32_t mbar_s = smem_u32(mbar);
    if (tid == 0) {
        asm volatile("mbarrier.init.shared.b64 [%0], 1;" :: "r"(mbar_s) : "memory");
        asm volatile("mbarrier.init.shared.b64 [%0], 1;" :: "r"(mbar_s + 8) : "memory");
    }
    __syncthreads();
    if (tid == 0) {
        asm volatile("mbarrier.arrive.expect_tx.shared.b64 _, [%0], 1024;" :: "r"(mbar_s) : "memory");
        asm volatile("mbarrier.arrive.expect_tx.shared.b64 _, [%0], 1024;" :: "r"(mbar_s + 8) : "memory");
    }
    __syncthreads();
    asm volatile("barrier.cluster.arrive.aligned;" ::: "memory");
    asm volatile("barrier.cluster.wait.aligned;"  ::: "memory");

    uint32_t dst = (uint32_t)(i >> 5);
    uint32_t lbase = smem_u32(pbuf) + (rank * 32u + (uint32_t)(i & 31)) * 4u;
    uint32_t raddr = mapa_u32(lbase, dst);   // parity stride 1024B
    uint32_t rmbar = mapa_u32(mbar_s, dst);  // parity stride 8B

    const int rowbase = b * NL;
    float4 s_cur = __ldg(reinterpret_cast<const float4*>(&g_sel[rowbase * NK]));
    float inv_c = 0.f, u_c = 0.f, h = 0.f;
    if (tid < 32) {
        inv_c = __ldg(&g_invn[rowbase * NH + jbase + tid]);
        u_c   = __ldg(&g_uin [rowbase * NH + jbase + tid]);
    }

    for (int t = 0; t < NL; t++) {
        const int row = rowbase + t;
        if (tid < 32) y_sm[tid] = h * inv_c;
        __syncthreads();

        const int d = (t < NL - 1) ? 1 : 0;
        float4 s_nxt = __ldg(reinterpret_cast<const float4*>(&g_sel[(row + d) * NK]));
        float inv_n = 0.f, u_n = 0.f;
        if (tid < 32) {
            inv_n = __ldg(&g_invn[(row + d) * NH + jbase + tid]);
            u_n   = __ldg(&g_uin [(row + d) * NH + jbase + tid]);
        }

        // k-decomposed matvec
        float k0 = 0.f, k1 = 0.f, k2 = 0.f, k3 = 0.f;
#pragma unroll
        for (int q = 0; q < 16; q++) {
            float yv = y_sm[half * 16 + q];
            k0 = fmaf(Areg[q].x, yv, k0);
            k1 = fmaf(Areg[q].y, yv, k1);
            k2 = fmaf(Areg[q].z, yv, k2);
            k3 = fmaf(Areg[q].w, yv, k3);
        }
        float acc = fmaf(s_cur.x, k0, fmaf(s_cur.y, k1,
                    fmaf(s_cur.z, k2, s_cur.w * k3)));
        acc += __shfl_xor_sync(0xffffffffu, acc, 1);

        const uint32_t poff = (uint32_t)(t & 1);
        if (half == 0) {
            asm volatile(
                "st.async.shared::cluster.mbarrier::complete_tx::bytes.b32 [%0], %1, [%2];"
                :: "r"(raddr + poff * 1024u), "r"(__float_as_uint(acc)),
                   "r"(rmbar + poff * 8u) : "memory");
        }

        // warp0 tail
        if (tid < 32) {
            const uint32_t ph = (uint32_t)((t >> 1) & 1);
            mbar_wait(mbar_s + poff * 8u, ph);
            if (tid == 0 && t + 2 < NL)
                asm volatile("mbarrier.arrive.expect_tx.shared.b64 _, [%0], 1024;"
                             :: "r"(mbar_s + poff * 8u) : "memory");
            const float* pb = &pbuf[poff][0][tid];
            float b0 = pb[0]   + pb[32];
            float b1 = pb[64]  + pb[96];
            float b2 = pb[128] + pb[160];
            float b3 = pb[192] + pb[224];
            float hv = u_c + ((b0 + b1) + (b2 + b3));
            out[row * NH + jbase + tid] = hv;
            h = hv; inv_c = inv_n; u_c = u_n;
        }
        s_cur = s_nxt;
    }

    asm volatile("barrier.cluster.arrive.aligned;" ::: "memory");
    asm volatile("barrier.cluster.wait.aligned;"  ::: "memory");
}

// ---------------- launch ----------------------------------------------------
extern "C" void kernel_launch(void* const* d_in, const int* in_sizes, int n_in,
                              void* d_out, int out_size)
{
    const float* x     = (const float*)d_in[0];   // (16,1024,512)
    const float* Wsel  = (const float*)d_in[1];   // (4,512)
    const float* bsel  = (const float*)d_in[2];   // (4,)
    const float* Wb    = (const float*)d_in[3];   // (256,512)
    const float* Adict = (const float*)d_in[4];   // (256,256,4)
    float* out = (float*)d_out;                   // (16,1024,256)

    sel_kernel<<<NROWS / 8, 256>>>(x, Wsel, bsel);
    uin_kernel<<<dim3(NROWS / 128, NH / 128), 256>>>(x, Wb);
    norm_kernel<<<dim3(32, 64), 256>>>(Adict);
    scan_kernel<<<NB * 8, 512>>>(Adict, out);     // 16 clusters x 8 CTAs
}